// round 15
// baseline (speedup 1.0000x reference)
#include <cuda_runtime.h>
#include <cuda_fp16.h>
#include <math.h>
#include <stdint.h>

// Problem constants
#define HSZ 512
#define ESZ 256
#define LSZ 64
#define OSZ 2
#define NH  4
#define HD  128   // HSZ/NH
#define BSN 1024
#define SS  100
#define TT  30

#define STRH 40   // hgemm smem row stride in halves
#define QSC 0.08838834764831845f

// ---------------------------------------------------------------------------
// Scratch (device globals; no allocations allowed)
// ---------------------------------------------------------------------------
__device__ __half g_K[(size_t)BSN * NH * HD * SS];  // [b,h,d/2,s,2] fp16
__device__ __half g_V[(size_t)BSN * NH * SS * HD];  // [b,h,s,d] fp16
__device__ __half g_f1[BSN * HSZ];
__device__ __half g_h1[2][BSN * HSZ];   // ping-pong
__device__ float  g_c1[BSN * HSZ];
__device__ __half g_h2[2][BSN * HSZ];   // ping-pong
__device__ float  g_c2[BSN * HSZ];
__device__ __half g_y1[BSN * (HSZ / 2)];
__device__ __half g_y2[BSN * (HSZ / 4)];
__device__ __half g_pg1[BSN * 4 * HSZ];  // partial gates: h1@whh + b  (fp16)
__device__ __half g_pg2[BSN * 4 * HSZ];  // partial gates: h2@whh + b  (fp16)
__device__ __half g_zf1[(size_t)BSN * TT * HSZ];  // z_t@fc1_B + bc, [b*TT+t, n]
// fp16 weights / inputs (converted per replay)
__device__ __half g_ench[(size_t)BSN * SS * ESZ];   // encoded fp16
__device__ __half g_zh[BSN * TT * LSZ];             // z fp16
__device__ __half g_qwh[HSZ * HSZ];
__device__ __half g_kwh[HSZ * ESZ];
__device__ __half g_vwh[HSZ * ESZ];
__device__ __half g_owTh[HSZ * HSZ];                // out_w^T fp16
__device__ __half g_fc1wh[HSZ * (HSZ + LSZ)];       // full fc1_w fp16
__device__ __half g_wch[HSZ * HSZ];                 // W_comb fp16
__device__ float  g_bc[HSZ];                        // combined fc1 bias
__device__ __half g_l1wih[4 * HSZ * HSZ];           // gate-interleaved fp16
__device__ __half g_l1whh[4 * HSZ * HSZ];
__device__ float  g_l1b[4 * HSZ];
__device__ __half g_l2wih[4 * HSZ * HSZ];
__device__ __half g_l2whh[4 * HSZ * HSZ];
__device__ float  g_l2b[4 * HSZ];
__device__ __half g_fc2awh[(HSZ / 2) * HSZ];
__device__ __half g_fc2bwh[(HSZ / 4) * (HSZ / 2)];

__device__ __forceinline__ void cp16(uint32_t dst, const void* src) {
    asm volatile("cp.async.cg.shared.global [%0], [%1], 16;"
                 :: "r"(dst), "l"(src));
}

__device__ __forceinline__ float sigm(float x) {
    return 1.f / (1.f + expf(-x));
}

__device__ __forceinline__ void mma16816(float* acc, const uint32_t* af,
                                         uint32_t b0, uint32_t b1) {
    asm volatile(
        "mma.sync.aligned.m16n8k16.row.col.f32.f16.f16.f32 "
        "{%0,%1,%2,%3}, {%4,%5,%6,%7}, {%8,%9}, {%0,%1,%2,%3};"
        : "+f"(acc[0]), "+f"(acc[1]), "+f"(acc[2]), "+f"(acc[3])
        : "r"(af[0]), "r"(af[1]), "r"(af[2]), "r"(af[3]), "r"(b0), "r"(b1));
}

// ---------------------------------------------------------------------------
// hgemm: unchanged proven engine (EPI 1/3/5/6/7 used)
// ---------------------------------------------------------------------------
template <int EPI, int BM, int BN>
__global__ __launch_bounds__(BM * BN / 32)
void hgemm(const __half* __restrict__ A1, int lda1, int K1,
           const __half* __restrict__ W1, int ldw1,
           const __half* __restrict__ A2, int lda2, int K2,
           const __half* __restrict__ W2, int ldw2,
           const float* __restrict__ b1,
           const __half* __restrict__ P, int ldp,
           __half* __restrict__ C, int N, float scale,
           __half* __restrict__ Hs, float* __restrict__ Cs)
{
    constexpr int T  = BM * BN / 32;
    constexpr int WM = BM / 32;

    extern __shared__ __half hsm[];
    __half* Asm = hsm;
    __half* Wsm = hsm + 2 * BM * STRH;

    const int tid  = threadIdx.x;
    const int lane = tid & 31;
    const int warp = tid >> 5;
    const int wm = (warp % WM) * 32;
    const int wn = (warp / WM) * 32;
    const int m0 = blockIdx.y * BM;
    const int n0 = blockIdx.x * BN;

    const int q = lane >> 2;
    const int r = lane & 3;

    const uint32_t As_b = (uint32_t)__cvta_generic_to_shared(Asm);
    const uint32_t Ws_b = (uint32_t)__cvta_generic_to_shared(Wsm);

    float acc[2][4][4];
#pragma unroll
    for (int i = 0; i < 2; i++)
#pragma unroll
        for (int j = 0; j < 4; j++)
#pragma unroll
            for (int f = 0; f < 4; f++) acc[i][j][f] = 0.f;

#pragma unroll 1
    for (int pass = 0; pass < 2; ++pass) {
        const __half* A = pass ? A2 : A1;
        const __half* W = pass ? W2 : W1;
        const int lda = pass ? lda2 : lda1;
        const int ldw = pass ? ldw2 : ldw1;
        const int K   = pass ? K2 : K1;
        if (K == 0) continue;

        auto load_tile = [&](int k0, int buf) {
#pragma unroll
            for (int i = tid; i < BM * 4; i += T) {
                int row = i >> 2, col = (i & 3) * 8;
                cp16(As_b + (uint32_t)(buf * BM * STRH + row * STRH + col) * 2,
                     A + (size_t)(m0 + row) * lda + k0 + col);
            }
#pragma unroll
            for (int i = tid; i < BN * 4; i += T) {
                int row = i >> 2, col = (i & 3) * 8;
                cp16(Ws_b + (uint32_t)(buf * BN * STRH + row * STRH + col) * 2,
                     W + (size_t)(n0 + row) * ldw + k0 + col);
            }
        };

        const int nk = K >> 5;
        load_tile(0, 0);
        asm volatile("cp.async.commit_group;" ::: "memory");

#pragma unroll 1
        for (int kt = 0; kt < nk; ++kt) {
            if (kt + 1 < nk) load_tile((kt + 1) << 5, (kt + 1) & 1);
            asm volatile("cp.async.commit_group;" ::: "memory");
            asm volatile("cp.async.wait_group 1;" ::: "memory");
            __syncthreads();

            const __half* Ab = Asm + (kt & 1) * BM * STRH;
            const __half* Wb = Wsm + (kt & 1) * BN * STRH;

#pragma unroll
            for (int ks = 0; ks < 32; ks += 16) {
                uint32_t af[2][4], bf[4][2];
#pragma unroll
                for (int mi = 0; mi < 2; ++mi) {
                    int mb = wm + mi * 16;
                    af[mi][0] = *(const uint32_t*)(Ab + (mb + q) * STRH + ks + 2 * r);
                    af[mi][1] = *(const uint32_t*)(Ab + (mb + q + 8) * STRH + ks + 2 * r);
                    af[mi][2] = *(const uint32_t*)(Ab + (mb + q) * STRH + ks + 2 * r + 8);
                    af[mi][3] = *(const uint32_t*)(Ab + (mb + q + 8) * STRH + ks + 2 * r + 8);
                }
#pragma unroll
                for (int ni = 0; ni < 4; ++ni) {
                    int nb = wn + ni * 8;
                    bf[ni][0] = *(const uint32_t*)(Wb + (nb + q) * STRH + ks + 2 * r);
                    bf[ni][1] = *(const uint32_t*)(Wb + (nb + q) * STRH + ks + 2 * r + 8);
                }
#pragma unroll
                for (int mi = 0; mi < 2; ++mi)
#pragma unroll
                    for (int ni = 0; ni < 4; ++ni)
                        mma16816(acc[mi][ni], af[mi], bf[ni][0], bf[ni][1]);
            }
            __syncthreads();
        }
    }

    if (EPI == 5) {
#pragma unroll
        for (int mi = 0; mi < 2; ++mi)
#pragma unroll
            for (int ni = 0; ni < 4; ++ni)
#pragma unroll
                for (int fr = 0; fr < 2; ++fr) {
                    int row = m0 + wm + mi * 16 + q + fr * 8;
                    int cb  = n0 + wn + ni * 8 + r * 2;
                    float2 pf = __half22float2(
                        *(const __half2*)(P + (size_t)row * ldp + cb));
                    float v0 = acc[mi][ni][fr * 2 + 0] + pf.x;
                    float v1 = acc[mi][ni][fr * 2 + 1] + pf.y;
                    bool ev = ((r & 1) == 0);
                    float a  = ev ? sigm(v0) : tanhf(v0);
                    float bb = sigm(v1);
                    float a2 = __shfl_xor_sync(0xffffffffu, a, 1);
                    float b2v = __shfl_xor_sync(0xffffffffu, bb, 1);
                    if (ev) {
                        size_t off = (size_t)row * HSZ + (cb >> 2);
                        float c2 = bb * Cs[off] + a * a2;
                        Cs[off] = c2;
                        Hs[off] = __float2half_rn(b2v * tanhf(c2));
                    }
                }
        return;
    }

    if (EPI == 6) {
#pragma unroll
        for (int mi = 0; mi < 2; ++mi)
#pragma unroll
            for (int ni = 0; ni < 4; ++ni)
#pragma unroll
                for (int fr = 0; fr < 2; ++fr) {
                    int m = m0 + wm + mi * 16 + q + fr * 8;
                    int n = n0 + wn + ni * 8 + r * 2;
                    float v0 = acc[mi][ni][fr * 2 + 0] + b1[n];
                    float v1 = acc[mi][ni][fr * 2 + 1] + b1[n + 1];
                    int b = m / SS, s = m - b * SS;
                    *reinterpret_cast<__half2*>(
                        C + (size_t)b * HSZ * SS + (size_t)n * SS + 2 * s) =
                        __floats2half2_rn(v0, v1);
                }
        return;
    }
    if (EPI == 7) {
#pragma unroll
        for (int mi = 0; mi < 2; ++mi)
#pragma unroll
            for (int ni = 0; ni < 4; ++ni)
#pragma unroll
                for (int fr = 0; fr < 2; ++fr) {
                    int m = m0 + wm + mi * 16 + q + fr * 8;
                    int n = n0 + wn + ni * 8 + r * 2;
                    float v0 = acc[mi][ni][fr * 2 + 0] + b1[n];
                    float v1 = acc[mi][ni][fr * 2 + 1] + b1[n + 1];
                    int b = m / SS, s = m - b * SS;
                    int h = n >> 7, d = n & 127;
                    *reinterpret_cast<__half2*>(
                        C + (size_t)b * HSZ * SS + (size_t)h * SS * HD
                          + (size_t)s * HD + d) = __floats2half2_rn(v0, v1);
                }
        return;
    }

    // EPI 1/3
#pragma unroll
    for (int mi = 0; mi < 2; ++mi)
#pragma unroll
        for (int ni = 0; ni < 4; ++ni)
#pragma unroll
            for (int fr = 0; fr < 2; ++fr) {
                int m = m0 + wm + mi * 16 + q + fr * 8;
                int n = n0 + wn + ni * 8 + r * 2;
                float v0 = acc[mi][ni][fr * 2 + 0];
                float v1 = acc[mi][ni][fr * 2 + 1];
                if (b1) { v0 += b1[n]; v1 += b1[n + 1]; }
                if (P) {
                    float2 pf = __half22float2(
                        *(const __half2*)(P + (size_t)m * ldp + n));
                    v0 += pf.x; v1 += pf.y;
                }
                if (EPI == 1) {
                    v0 = (v0 >= 0.f) ? v0 : 0.2f * v0;
                    v1 = (v1 >= 0.f) ? v1 : 0.2f * v1;
                }
                *reinterpret_cast<__half2*>(C + (size_t)m * N + n) =
                    __floats2half2_rn(v0, v1);
            }
}

// ---------------------------------------------------------------------------
// Fused qproj + attention + fc1.  One CTA per 8 batch rows (128 CTAs x 512).
//   phase1: q = (h2 @ qw^T + qb) * QSC           (mma, M=8 padded to 16)
//   phase2: att = softmax(qK)V  per (row, head)  (4 groups of 128 threads)
//   phase3: f1 = lrelu(att @ wc^T + zf1[t])      (mma)
// ---------------------------------------------------------------------------
#define STR2 520

__global__ __launch_bounds__(512)
void qaf_kernel(const __half* __restrict__ h2r,
                const __half* __restrict__ qw,   // [n][k] fp16
                const float*  __restrict__ qb,
                const __half* __restrict__ Kt,   // [b,h,d/2,s,2]
                const __half* __restrict__ V,    // [b,h,s,d]
                const __half* __restrict__ wc,   // [n][k] fp16
                const __half* __restrict__ zf1,  // [b*TT+t][n]
                __half* __restrict__ f1, int t)
{
    __shared__ __half h2s[16 * STR2];   // phase1 A; aliased as att for phase3
    __shared__ __half qs_all[8 * STR2];
    __shared__ float qsf[4][128];
    __shared__ float sc[4][128];
    __shared__ float red[4][128];

    const int tid  = threadIdx.x;
    const int lane = tid & 31;
    const int warp = tid >> 5;
    const int q = lane >> 2;
    const int r = lane & 3;
    const int wn = warp * 32;
    const int b0 = blockIdx.x * 8;

    // load h2 rows 0..7 (full 512 cols: 512 threads x 1 uint4 each) and
    // zero padding rows 8..15 (another uint4 per thread)
    {
        int row = tid >> 6;           // 0..7
        int cc  = (tid & 63) * 8;     // 0..504
        *(uint4*)&h2s[row * STR2 + cc] =
            *(const uint4*)(h2r + (size_t)(b0 + row) * HSZ + cc);
        *(uint4*)&h2s[(8 + row) * STR2 + cc] = make_uint4(0, 0, 0, 0);
    }
    __syncthreads();

    // ---- phase 1: qproj ----
    {
        float acc[4][4];
#pragma unroll
        for (int i = 0; i < 4; ++i)
#pragma unroll
            for (int f = 0; f < 4; ++f) acc[i][f] = 0.f;

#pragma unroll 4
        for (int k = 0; k < HSZ; k += 16) {
            uint32_t af[4];
            af[0] = *(const uint32_t*)&h2s[q * STR2 + k + 2 * r];
            af[1] = *(const uint32_t*)&h2s[(q + 8) * STR2 + k + 2 * r];
            af[2] = *(const uint32_t*)&h2s[q * STR2 + k + 2 * r + 8];
            af[3] = *(const uint32_t*)&h2s[(q + 8) * STR2 + k + 2 * r + 8];
#pragma unroll
            for (int ni = 0; ni < 4; ++ni) {
                int n = wn + ni * 8;
                uint32_t bf0 = *(const uint32_t*)(qw + (size_t)(n + q) * HSZ + k + 2 * r);
                uint32_t bf1 = *(const uint32_t*)(qw + (size_t)(n + q) * HSZ + k + 2 * r + 8);
                mma16816(acc[ni], af, bf0, bf1);
            }
        }
#pragma unroll
        for (int ni = 0; ni < 4; ++ni) {
            int c = wn + ni * 8 + 2 * r;
            float v0 = (acc[ni][0] + qb[c]) * QSC;
            float v1 = (acc[ni][1] + qb[c + 1]) * QSC;
            *(__half2*)&qs_all[q * STR2 + c] = __floats2half2_rn(v0, v1);
        }
    }
    __syncthreads();

    // ---- phase 2: attention (group g = head, 128 threads each) ----
    const int g  = tid >> 7;
    const int gt = tid & 127;
    __half* atts = h2s;   // alias; rows 8..15 remain zero

#pragma unroll 1
    for (int rr = 0; rr < 8; ++rr) {
        qsf[g][gt] = __half2float(qs_all[rr * STR2 + g * 128 + gt]);
        __syncthreads();

        const int u = (b0 + rr) * NH + g;
        float a = 0.f;
        const __half2* Kp2 = (const __half2*)(Kt + (size_t)u * HD * SS);
        if (gt < SS) {
            float a0 = 0.f, a1 = 0.f;
#pragma unroll 8
            for (int dp = 0; dp < 64; dp += 2) {
                float2 f0 = __half22float2(Kp2[(dp + 0) * SS + gt]);
                float2 f1v = __half22float2(Kp2[(dp + 1) * SS + gt]);
                a0 += qsf[g][2 * dp + 0] * f0.x + qsf[g][2 * dp + 1] * f0.y;
                a1 += qsf[g][2 * dp + 2] * f1v.x + qsf[g][2 * dp + 3] * f1v.y;
            }
            a = a0 + a1;
        }
        sc[g][gt]  = a;
        red[g][gt] = (gt < SS) ? a : -1e30f;
        __syncthreads();
#pragma unroll
        for (int off = 64; off > 0; off >>= 1) {
            if (gt < off) red[g][gt] = fmaxf(red[g][gt], red[g][gt + off]);
            __syncthreads();
        }
        const float mx = red[g][0];
        __syncthreads();

        float e = (gt < SS) ? expf(sc[g][gt] - mx) : 0.f;
        sc[g][gt]  = e;
        red[g][gt] = e;
        __syncthreads();
#pragma unroll
        for (int off = 64; off > 0; off >>= 1) {
            if (gt < off) red[g][gt] += red[g][gt + off];
            __syncthreads();
        }
        const float inv = 1.f / red[g][0];

        float o0 = 0.f, o1 = 0.f, o2 = 0.f, o3 = 0.f;
        const __half* Vp = V + (size_t)u * SS * HD + gt;
#pragma unroll 2
        for (int s = 0; s < SS; s += 4) {
            o0 += sc[g][s + 0] * __half2float(Vp[(size_t)(s + 0) * HD]);
            o1 += sc[g][s + 1] * __half2float(Vp[(size_t)(s + 1) * HD]);
            o2 += sc[g][s + 2] * __half2float(Vp[(size_t)(s + 2) * HD]);
            o3 += sc[g][s + 3] * __half2float(Vp[(size_t)(s + 3) * HD]);
        }
        atts[rr * STR2 + g * 128 + gt] =
            __float2half_rn(((o0 + o1) + (o2 + o3)) * inv);
        __syncthreads();
    }

    // ---- phase 3: fc1 ----
    {
        float acc[4][4];
#pragma unroll
        for (int i = 0; i < 4; ++i)
#pragma unroll
            for (int f = 0; f < 4; ++f) acc[i][f] = 0.f;

#pragma unroll 4
        for (int k = 0; k < HSZ; k += 16) {
            uint32_t af[4];
            af[0] = *(const uint32_t*)&atts[q * STR2 + k + 2 * r];
            af[1] = *(const uint32_t*)&atts[(q + 8) * STR2 + k + 2 * r];
            af[2] = *(const uint32_t*)&atts[q * STR2 + k + 2 * r + 8];
            af[3] = *(const uint32_t*)&atts[(q + 8) * STR2 + k + 2 * r + 8];
#pragma unroll
            for (int ni = 0; ni < 4; ++ni) {
                int n = wn + ni * 8;
                uint32_t bf0 = *(const uint32_t*)(wc + (size_t)(n + q) * HSZ + k + 2 * r);
                uint32_t bf1 = *(const uint32_t*)(wc + (size_t)(n + q) * HSZ + k + 2 * r + 8);
                mma16816(acc[ni], af, bf0, bf1);
            }
        }
#pragma unroll
        for (int ni = 0; ni < 4; ++ni) {
            int c = wn + ni * 8 + 2 * r;
            size_t zoff = ((size_t)(b0 + q) * TT + t) * HSZ + c;
            float2 pf = __half22float2(*(const __half2*)(zf1 + zoff));
            float v0 = acc[ni][0] + pf.x;
            float v1 = acc[ni][1] + pf.y;
            v0 = (v0 >= 0.f) ? v0 : 0.2f * v0;
            v1 = (v1 >= 0.f) ? v1 : 0.2f * v1;
            *(__half2*)(f1 + (size_t)(b0 + q) * HSZ + c) = __floats2half2_rn(v0, v1);
        }
    }
}

// ---------------------------------------------------------------------------
// Final tiny layer (coalesced)
// ---------------------------------------------------------------------------
__global__ __launch_bounds__(256)
void fc2c_kernel(const __half* __restrict__ y2, const float* __restrict__ w,
                 const float* __restrict__ b, float* __restrict__ out, int t)
{
    const int warp = threadIdx.x >> 5, lane = threadIdx.x & 31;
    const int m = blockIdx.x * 8 + warp;
    const __half* yr = y2 + (size_t)m * (HSZ / 4);
    float a0 = 0.f, a1 = 0.f;
#pragma unroll
    for (int d = lane; d < HSZ / 4; d += 32) {
        float v = __half2float(yr[d]);
        a0 += v * w[d];
        a1 += v * w[HSZ / 4 + d];
    }
#pragma unroll
    for (int off = 16; off; off >>= 1) {
        a0 += __shfl_down_sync(0xffffffff, a0, off);
        a1 += __shfl_down_sync(0xffffffff, a1, off);
    }
    if (lane == 0) {
        out[(size_t)m * TT * OSZ + t * OSZ + 0] = tanhf(a0 + b[0]);
        out[(size_t)m * TT * OSZ + t * OSZ + 1] = tanhf(a1 + b[1]);
    }
}

// ---------------------------------------------------------------------------
// Precompute kernels
// ---------------------------------------------------------------------------
__global__ void cvt2h(const float* __restrict__ in, __half* __restrict__ out,
                      int n4)
{
    int i = blockIdx.x * blockDim.x + threadIdx.x;
    if (i < n4) {
        float4 v = reinterpret_cast<const float4*>(in)[i];
        reinterpret_cast<__half2*>(out)[2 * i]     = __floats2half2_rn(v.x, v.y);
        reinterpret_cast<__half2*>(out)[2 * i + 1] = __floats2half2_rn(v.z, v.w);
    }
}

__global__ void transpose512h(const float* __restrict__ in, __half* __restrict__ out)
{
    __shared__ float t[32][33];
    int x = blockIdx.x * 32 + threadIdx.x;
    int y0 = blockIdx.y * 32 + threadIdx.y;
#pragma unroll
    for (int i = 0; i < 4; ++i)
        t[threadIdx.y + i * 8][threadIdx.x] = in[(size_t)(y0 + i * 8) * HSZ + x];
    __syncthreads();
    x = blockIdx.y * 32 + threadIdx.x;
    int y1 = blockIdx.x * 32 + threadIdx.y;
#pragma unroll
    for (int i = 0; i < 4; ++i)
        out[(size_t)(y1 + i * 8) * HSZ + x] =
            __float2half_rn(t[threadIdx.x][threadIdx.y + i * 8]);
}

__global__ void prep_fc1b(const float* __restrict__ fc1_w,
                          const float* __restrict__ out_b,
                          const float* __restrict__ fc1_b,
                          float* __restrict__ bc)
{
    const int warp = threadIdx.x >> 5, lane = threadIdx.x & 31;
    const int j = blockIdx.x * 8 + warp;
    float s = 0.f;
#pragma unroll
    for (int m = lane; m < HSZ; m += 32)
        s += fc1_w[(size_t)j * (HSZ + LSZ) + m] * out_b[m];
#pragma unroll
    for (int off = 16; off; off >>= 1)
        s += __shfl_down_sync(0xffffffff, s, off);
    if (lane == 0) bc[j] = s + fc1_b[j];
}

__global__ void prep_lstm(const float* __restrict__ wih, const float* __restrict__ whh,
                          const float* __restrict__ bih, const float* __restrict__ bhh,
                          __half* __restrict__ wih_p, __half* __restrict__ whh_p,
                          float* __restrict__ b_p)
{
    int idx = blockIdx.x * blockDim.x + threadIdx.x;
    int c = idx >> 9, k = idx & 511;
    int orig = (c & 3) * HSZ + (c >> 2);
    wih_p[idx] = __float2half_rn(wih[(size_t)orig * HSZ + k]);
    whh_p[idx] = __float2half_rn(whh[(size_t)orig * HSZ + k]);
    if (k == 0) b_p[c] = bih[orig] + bhh[orig];
}

__global__ void init_pg(const float* __restrict__ b1, const float* __restrict__ b2)
{
    int idx = blockIdx.x * blockDim.x + threadIdx.x;
    int c = idx & (4 * HSZ - 1);
    g_pg1[idx] = __float2half_rn(b1[c]);
    g_pg2[idx] = __float2half_rn(b2[c]);
}

__global__ void zero_states()
{
    int idx = blockIdx.x * blockDim.x + threadIdx.x;
    if (idx < BSN * HSZ) {
        g_h1[0][idx] = __half(0.f); g_h1[1][idx] = __half(0.f);
        g_h2[0][idx] = __half(0.f); g_h2[1][idx] = __half(0.f);
        g_c1[idx] = 0.f;            g_c2[idx] = 0.f;
    }
}

// ---------------------------------------------------------------------------
// Static-init resources
// ---------------------------------------------------------------------------
struct Res {
    cudaStream_t s2 = nullptr, s3 = nullptr;
    cudaEvent_t evF = nullptr, evA = nullptr, evJ = nullptr;
    cudaEvent_t evL1 = nullptr, evP1 = nullptr, evL2 = nullptr, evP2 = nullptr;
    bool ok = false;
    Res() {
        if (cudaStreamCreateWithFlags(&s2, cudaStreamNonBlocking) != cudaSuccess) return;
        if (cudaStreamCreateWithFlags(&s3, cudaStreamNonBlocking) != cudaSuccess) return;
        if (cudaEventCreateWithFlags(&evF, cudaEventDisableTiming) != cudaSuccess) return;
        if (cudaEventCreateWithFlags(&evA, cudaEventDisableTiming) != cudaSuccess) return;
        if (cudaEventCreateWithFlags(&evJ, cudaEventDisableTiming) != cudaSuccess) return;
        if (cudaEventCreateWithFlags(&evL1, cudaEventDisableTiming) != cudaSuccess) return;
        if (cudaEventCreateWithFlags(&evP1, cudaEventDisableTiming) != cudaSuccess) return;
        if (cudaEventCreateWithFlags(&evL2, cudaEventDisableTiming) != cudaSuccess) return;
        if (cudaEventCreateWithFlags(&evP2, cudaEventDisableTiming) != cudaSuccess) return;
        ok = true;
    }
};
static Res g_res;

// ---------------------------------------------------------------------------
extern "C" void kernel_launch(void* const* d_in, const int* in_sizes, int n_in,
                              void* d_out, int out_size)
{
    (void)in_sizes; (void)n_in; (void)out_size;
    const float* encoded = (const float*)d_in[0];
    const float* z       = (const float*)d_in[1];
    const float* q_w     = (const float*)d_in[2];
    const float* k_w     = (const float*)d_in[3];
    const float* v_w     = (const float*)d_in[4];
    const float* q_b     = (const float*)d_in[5];
    const float* k_b     = (const float*)d_in[6];
    const float* v_b     = (const float*)d_in[7];
    const float* out_w   = (const float*)d_in[8];
    const float* out_b   = (const float*)d_in[9];
    const float* fc1_w   = (const float*)d_in[10];
    const float* fc1_b   = (const float*)d_in[11];
    const float* l1_wih  = (const float*)d_in[12];
    const float* l1_whh  = (const float*)d_in[13];
    const float* l1_bih  = (const float*)d_in[14];
    const float* l1_bhh  = (const float*)d_in[15];
    const float* l2_wih  = (const float*)d_in[16];
    const float* l2_whh  = (const float*)d_in[17];
    const float* l2_bih  = (const float*)d_in[18];
    const float* l2_bhh  = (const float*)d_in[19];
    const float* fc2a_w  = (const float*)d_in[20];
    const float* fc2a_b  = (const float*)d_in[21];
    const float* fc2b_w  = (const float*)d_in[22];
    const float* fc2b_b  = (const float*)d_in[23];
    const float* fc2c_w  = (const float*)d_in[24];
    const float* fc2c_b  = (const float*)d_in[25];
    float* out = (float*)d_out;

    __half *pK, *pV, *pf1, *ph1, *ph2, *py1, *py2, *ppg1, *ppg2, *pzf1;
    __half *pench, *pzh, *pqwh, *pkwh, *pvwh, *powTh, *pfc1wh, *pwch;
    __half *pl1wih, *pl1whh, *pl2wih, *pl2whh, *pfc2awh, *pfc2bwh;
    float *pc1, *pc2, *pbc, *pl1b, *pl2b;
    cudaGetSymbolAddress((void**)&pK,  g_K);
    cudaGetSymbolAddress((void**)&pV,  g_V);
    cudaGetSymbolAddress((void**)&pf1, g_f1);
    cudaGetSymbolAddress((void**)&ph1, g_h1);
    cudaGetSymbolAddress((void**)&pc1, g_c1);
    cudaGetSymbolAddress((void**)&ph2, g_h2);
    cudaGetSymbolAddress((void**)&pc2, g_c2);
    cudaGetSymbolAddress((void**)&py1, g_y1);
    cudaGetSymbolAddress((void**)&py2, g_y2);
    cudaGetSymbolAddress((void**)&ppg1, g_pg1);
    cudaGetSymbolAddress((void**)&ppg2, g_pg2);
    cudaGetSymbolAddress((void**)&pzf1, g_zf1);
    cudaGetSymbolAddress((void**)&pench, g_ench);
    cudaGetSymbolAddress((void**)&pzh,   g_zh);
    cudaGetSymbolAddress((void**)&pqwh,  g_qwh);
    cudaGetSymbolAddress((void**)&pkwh,  g_kwh);
    cudaGetSymbolAddress((void**)&pvwh,  g_vwh);
    cudaGetSymbolAddress((void**)&powTh, g_owTh);
    cudaGetSymbolAddress((void**)&pfc1wh, g_fc1wh);
    cudaGetSymbolAddress((void**)&pwch,  g_wch);
    cudaGetSymbolAddress((void**)&pbc,   g_bc);
    cudaGetSymbolAddress((void**)&pl1wih, g_l1wih);
    cudaGetSymbolAddress((void**)&pl1whh, g_l1whh);
    cudaGetSymbolAddress((void**)&pl1b,   g_l1b);
    cudaGetSymbolAddress((void**)&pl2wih, g_l2wih);
    cudaGetSymbolAddress((void**)&pl2whh, g_l2whh);
    cudaGetSymbolAddress((void**)&pl2b,   g_l2b);
    cudaGetSymbolAddress((void**)&pfc2awh, g_fc2awh);
    cudaGetSymbolAddress((void**)&pfc2bwh, g_fc2bwh);

    const size_t SMH64   = (size_t)(4 * 64) * STRH * sizeof(__half);   // 20480
    const size_t SMH1212 = (size_t)(4 * 128) * STRH * sizeof(__half);  // 40960

    const bool dual = g_res.ok;
    cudaStream_t s2 = dual ? g_res.s2 : (cudaStream_t)0;
    cudaStream_t s3 = dual ? g_res.s3 : (cudaStream_t)0;

    // ---- precomputes ----
    zero_states<<<(BSN * HSZ + 255) / 256, 256>>>();
    cvt2h<<<((BSN * SS * ESZ / 4) + 255) / 256, 256>>>(encoded, pench, BSN * SS * ESZ / 4);
    cvt2h<<<((BSN * TT * LSZ / 4) + 255) / 256, 256>>>(z, pzh, BSN * TT * LSZ / 4);
    cvt2h<<<((HSZ * HSZ / 4) + 255) / 256, 256>>>(q_w, pqwh, HSZ * HSZ / 4);
    cvt2h<<<((HSZ * ESZ / 4) + 255) / 256, 256>>>(k_w, pkwh, HSZ * ESZ / 4);
    cvt2h<<<((HSZ * ESZ / 4) + 255) / 256, 256>>>(v_w, pvwh, HSZ * ESZ / 4);
    cvt2h<<<((HSZ * (HSZ + LSZ) / 4) + 255) / 256, 256>>>(fc1_w, pfc1wh, HSZ * (HSZ + LSZ) / 4);
    cvt2h<<<((HSZ / 2 * HSZ / 4) + 255) / 256, 256>>>(fc2a_w, pfc2awh, HSZ / 2 * HSZ / 4);
    cvt2h<<<((HSZ / 4 * HSZ / 2 / 4) + 255) / 256, 256>>>(fc2b_w, pfc2bwh, HSZ / 4 * HSZ / 2 / 4);
    transpose512h<<<dim3(16, 16), dim3(32, 8)>>>(out_w, powTh);
    prep_fc1b<<<64, 256>>>(fc1_w, out_b, fc1_b, pbc);
    prep_lstm<<<4096, 256>>>(l1_wih, l1_whh, l1_bih, l1_bhh, pl1wih, pl1whh, pl1b);
    prep_lstm<<<4096, 256>>>(l2_wih, l2_whh, l2_bih, l2_bhh, pl2wih, pl2whh, pl2b);
    init_pg<<<(BSN * 4 * HSZ) / 256, 256>>>(pl1b, pl2b);
    // W_comb = fc1_A @ out_w
    hgemm<3, 64, 64><<<dim3(8, 8), 128, SMH64>>>(
        pfc1wh, HSZ + LSZ, HSZ, powTh, HSZ, nullptr, 0, 0, nullptr, 0,
        nullptr, nullptr, 0, pwch, HSZ, 0.f, nullptr, nullptr);
    // zf1[b*TT+t, n] = z[b,t,:] @ fc1_B^T + bc
    hgemm<3, 128, 128><<<dim3(HSZ / 128, (BSN * TT) / 128), 512, SMH1212>>>(
        pzh, LSZ, LSZ, pfc1wh + HSZ, HSZ + LSZ, nullptr, 0, 0, nullptr, 0,
        pbc, nullptr, 0, pzf1, HSZ, 0.f, nullptr, nullptr);

    // ---- K/V projections ----
    {
        dim3 grid(HSZ / 128, (BSN * SS) / 128);
        hgemm<6, 128, 128><<<grid, 512, SMH1212>>>(
            pench, ESZ, ESZ, pkwh, ESZ, nullptr, 0, 0, nullptr, 0,
            k_b, nullptr, 0, pK, HSZ, 0.f, nullptr, nullptr);
        hgemm<7, 128, 128><<<grid, 512, SMH1212>>>(
            pench, ESZ, ESZ, pvwh, ESZ, nullptr, 0, 0, nullptr, 0,
            v_b, nullptr, 0, pV, HSZ, 0.f, nullptr, nullptr);
    }

    dim3 gG(4 * HSZ / 128, BSN / 128);       // 16 x 8
    dim3 gA(HSZ / 2 / 64, BSN / 64);         // 4 x 16
    dim3 gB(HSZ / 4 / 64, BSN / 64);         // 2 x 16

    const size_t HB = (size_t)BSN * HSZ;

    for (int t = 0; t < TT; ++t) {
        __half* h1w = ph1 + ((t + 1) & 1) * HB;
        __half* h2r = ph2 + (t & 1) * HB;
        __half* h2w = ph2 + ((t + 1) & 1) * HB;

        // fused qproj + attention + fc1 (critical)
        qaf_kernel<<<BSN / 8, 512>>>(h2r, pqwh, q_b, pK, pV, pwch, pzf1, pf1, t);

        // LSTM1 (critical): gates = f1 @ wih + pg1
        if (dual && t > 0) cudaStreamWaitEvent(0, g_res.evP1, 0);
        hgemm<5, 128, 128><<<gG, 512, SMH1212>>>(
            pf1, HSZ, HSZ, pl1wih, HSZ, nullptr, 0, 0, nullptr, 0,
            nullptr, ppg1, 4 * HSZ, nullptr, 4 * HSZ, 0.f, h1w, pc1);
        if (dual) {
            cudaEventRecord(g_res.evL1, 0);
            cudaStreamWaitEvent(s3, g_res.evL1, 0);
        }
        // off-critical: pg1 <- h1(t) @ l1whh + b
        hgemm<3, 128, 128><<<gG, 512, SMH1212, s3>>>(
            h1w, HSZ, HSZ, pl1whh, HSZ, nullptr, 0, 0, nullptr, 0,
            pl1b, nullptr, 0, ppg1, 4 * HSZ, 0.f, nullptr, nullptr);
        if (dual) cudaEventRecord(g_res.evP1, s3);

        // LSTM2 (critical)
        if (dual && t > 0) {
            cudaStreamWaitEvent(0, g_res.evA, 0);
            cudaStreamWaitEvent(0, g_res.evP2, 0);
        }
        hgemm<5, 128, 128><<<gG, 512, SMH1212>>>(
            h1w, HSZ, HSZ, pl2wih, HSZ, nullptr, 0, 0, nullptr, 0,
            nullptr, ppg2, 4 * HSZ, nullptr, 4 * HSZ, 0.f, h2w, pc2);
        if (dual) {
            cudaEventRecord(g_res.evL2, 0);
            cudaStreamWaitEvent(s3, g_res.evL2, 0);
        }
        // off-critical: pg2 <- h2(t) @ l2whh + b
        hgemm<3, 128, 128><<<gG, 512, SMH1212, s3>>>(
            h2w, HSZ, HSZ, pl2whh, HSZ, nullptr, 0, 0, nullptr, 0,
            pl2b, nullptr, 0, ppg2, 4 * HSZ, 0.f, nullptr, nullptr);
        if (dual) cudaEventRecord(g_res.evP2, s3);

        // fc2 tail on s2, overlaps next step
        if (dual) {
            cudaEventRecord(g_res.evF, 0);
            cudaStreamWaitEvent(s2, g_res.evF, 0);
        }
        hgemm<1, 64, 64><<<gA, 128, SMH64, s2>>>(
            h2w, HSZ, HSZ, pfc2awh, HSZ, nullptr, 0, 0, nullptr, 0,
            fc2a_b, nullptr, 0, py1, HSZ / 2, 0.f, nullptr, nullptr);
        if (dual) cudaEventRecord(g_res.evA, s2);
        hgemm<1, 64, 64><<<gB, 128, SMH64, s2>>>(
            py1, HSZ / 2, HSZ / 2, pfc2bwh, HSZ / 2, nullptr, 0, 0, nullptr, 0,
            fc2b_b, nullptr, 0, py2, HSZ / 4, 0.f, nullptr, nullptr);
        fc2c_kernel<<<BSN / 8, 256, 0, s2>>>(py2, fc2c_w, fc2c_b, out, t);
        if (dual) cudaEventRecord(g_res.evJ, s2);
    }
    if (dual) {
        cudaStreamWaitEvent(0, g_res.evJ, 0);
        cudaStreamWaitEvent(0, g_res.evP1, 0);
        cudaStreamWaitEvent(0, g_res.evP2, 0);
    }
}

// round 16
// speedup vs baseline: 2.2684x; 2.2684x over previous
#include <cuda_runtime.h>
#include <cuda_fp16.h>
#include <math.h>
#include <stdint.h>

// Problem constants
#define HSZ 512
#define ESZ 256
#define LSZ 64
#define OSZ 2
#define NH  4
#define HD  128   // HSZ/NH
#define BSN 1024
#define SS  100
#define TT  30

#define STRH 40  // smem row stride in halves (32 + 8 pad: conflict-free)

// ---------------------------------------------------------------------------
// Scratch (device globals; no allocations allowed)
// ---------------------------------------------------------------------------
__device__ __half g_K[(size_t)BSN * NH * HD * SS];  // [b,h,d/2,s,2] fp16
__device__ __half g_V[(size_t)BSN * NH * SS * HD];  // [b,h,s,d] fp16
__device__ __half g_q[BSN * HSZ];
__device__ __half g_att[BSN * HSZ];
__device__ __half g_f1[BSN * HSZ];
__device__ __half g_h1[2][BSN * HSZ];               // ping-pong
__device__ float  g_c1[BSN * HSZ];
__device__ __half g_h2[(size_t)(TT + 1) * BSN * HSZ];  // history: [t][b][n]
__device__ float  g_c2[BSN * HSZ];
__device__ __half g_y1[(size_t)BSN * TT * (HSZ / 2)];  // batched fc2a out
__device__ __half g_y2[(size_t)BSN * TT * (HSZ / 4)];  // batched fc2b out
__device__ __half g_zf1[(size_t)BSN * TT * HSZ];    // z_t@fc1_B + bc
// fp16 weights / inputs (converted per replay)
__device__ __half g_ench[(size_t)BSN * SS * ESZ];
__device__ __half g_zh[BSN * TT * LSZ];
__device__ __half g_qwh[HSZ * HSZ];
__device__ __half g_kwh[HSZ * ESZ];
__device__ __half g_vwh[HSZ * ESZ];
__device__ __half g_owTh[HSZ * HSZ];
__device__ __half g_fc1wh[HSZ * (HSZ + LSZ)];
__device__ __half g_wch[HSZ * HSZ];
__device__ float  g_bc[HSZ];
__device__ __half g_l1wih[4 * HSZ * HSZ];           // gate-interleaved fp16
__device__ __half g_l1whh[4 * HSZ * HSZ];
__device__ float  g_l1b[4 * HSZ];
__device__ __half g_l2wih[4 * HSZ * HSZ];
__device__ __half g_l2whh[4 * HSZ * HSZ];
__device__ float  g_l2b[4 * HSZ];
__device__ __half g_fc2awh[(HSZ / 2) * HSZ];
__device__ __half g_fc2bwh[(HSZ / 4) * (HSZ / 2)];

__device__ __forceinline__ void cp16(uint32_t dst, const void* src) {
    asm volatile("cp.async.cg.shared.global [%0], [%1], 16;"
                 :: "r"(dst), "l"(src));
}

__device__ __forceinline__ float sigm(float x) {
    return 1.f / (1.f + expf(-x));
}

// ---------------------------------------------------------------------------
// fp16 tensor-core GEMM (mma.m16n8k16, fp32 accum), cp.async double-buffered:
//   C = act( A1 @ W1^T [+ A2 @ W2^T] + b1 [+ P] )
// A row-major [M,K] fp16, W row-major [N,K] fp16.  BK=32 halves.
// Warps: (BM/32) x (BN/32), warp tile 32x32, threads = BM*BN/32.
// EPI: 1 lrelu fp16, 2 scale fp16, 3 plain fp16,
//      5 LSTM cell (gate-interleaved; float bias b1; Hs fp16, Cs fp32),
//      6 K-layout fp16 (d-pair interleaved), 7 V-layout fp16
// ---------------------------------------------------------------------------
template <int EPI, int BM, int BN>
__global__ __launch_bounds__(BM * BN / 32)
void hgemm(const __half* __restrict__ A1, int lda1, int K1,
           const __half* __restrict__ W1, int ldw1,
           const __half* __restrict__ A2, int lda2, int K2,
           const __half* __restrict__ W2, int ldw2,
           const float* __restrict__ b1,
           const __half* __restrict__ P, int ldp,
           __half* __restrict__ C, int N, float scale,
           __half* __restrict__ Hs, float* __restrict__ Cs)
{
    constexpr int T  = BM * BN / 32;
    constexpr int WM = BM / 32;

    extern __shared__ __half hsm[];
    __half* Asm = hsm;
    __half* Wsm = hsm + 2 * BM * STRH;

    const int tid  = threadIdx.x;
    const int lane = tid & 31;
    const int warp = tid >> 5;
    const int wm = (warp % WM) * 32;
    const int wn = (warp / WM) * 32;
    const int m0 = blockIdx.y * BM;
    const int n0 = blockIdx.x * BN;

    const int q = lane >> 2;
    const int r = lane & 3;

    const uint32_t As_b = (uint32_t)__cvta_generic_to_shared(Asm);
    const uint32_t Ws_b = (uint32_t)__cvta_generic_to_shared(Wsm);

    float acc[2][4][4];
#pragma unroll
    for (int i = 0; i < 2; i++)
#pragma unroll
        for (int j = 0; j < 4; j++)
#pragma unroll
            for (int f = 0; f < 4; f++) acc[i][j][f] = 0.f;

#pragma unroll 1
    for (int pass = 0; pass < 2; ++pass) {
        const __half* A = pass ? A2 : A1;
        const __half* W = pass ? W2 : W1;
        const int lda = pass ? lda2 : lda1;
        const int ldw = pass ? ldw2 : ldw1;
        const int K   = pass ? K2 : K1;
        if (K == 0) continue;

        auto load_tile = [&](int k0, int buf) {
#pragma unroll
            for (int i = tid; i < BM * 4; i += T) {
                int row = i >> 2, col = (i & 3) * 8;
                cp16(As_b + (uint32_t)(buf * BM * STRH + row * STRH + col) * 2,
                     A + (size_t)(m0 + row) * lda + k0 + col);
            }
#pragma unroll
            for (int i = tid; i < BN * 4; i += T) {
                int row = i >> 2, col = (i & 3) * 8;
                cp16(Ws_b + (uint32_t)(buf * BN * STRH + row * STRH + col) * 2,
                     W + (size_t)(n0 + row) * ldw + k0 + col);
            }
        };

        const int nk = K >> 5;
        load_tile(0, 0);
        asm volatile("cp.async.commit_group;" ::: "memory");

#pragma unroll 1
        for (int kt = 0; kt < nk; ++kt) {
            if (kt + 1 < nk) load_tile((kt + 1) << 5, (kt + 1) & 1);
            asm volatile("cp.async.commit_group;" ::: "memory");
            asm volatile("cp.async.wait_group 1;" ::: "memory");
            __syncthreads();

            const __half* Ab = Asm + (kt & 1) * BM * STRH;
            const __half* Wb = Wsm + (kt & 1) * BN * STRH;

#pragma unroll
            for (int ks = 0; ks < 32; ks += 16) {
                uint32_t af[2][4], bf[4][2];
#pragma unroll
                for (int mi = 0; mi < 2; ++mi) {
                    int mb = wm + mi * 16;
                    af[mi][0] = *(const uint32_t*)(Ab + (mb + q) * STRH + ks + 2 * r);
                    af[mi][1] = *(const uint32_t*)(Ab + (mb + q + 8) * STRH + ks + 2 * r);
                    af[mi][2] = *(const uint32_t*)(Ab + (mb + q) * STRH + ks + 2 * r + 8);
                    af[mi][3] = *(const uint32_t*)(Ab + (mb + q + 8) * STRH + ks + 2 * r + 8);
                }
#pragma unroll
                for (int ni = 0; ni < 4; ++ni) {
                    int nb = wn + ni * 8;
                    bf[ni][0] = *(const uint32_t*)(Wb + (nb + q) * STRH + ks + 2 * r);
                    bf[ni][1] = *(const uint32_t*)(Wb + (nb + q) * STRH + ks + 2 * r + 8);
                }
#pragma unroll
                for (int mi = 0; mi < 2; ++mi)
#pragma unroll
                    for (int ni = 0; ni < 4; ++ni) {
                        asm volatile(
                            "mma.sync.aligned.m16n8k16.row.col.f32.f16.f16.f32 "
                            "{%0,%1,%2,%3}, {%4,%5,%6,%7}, {%8,%9}, {%0,%1,%2,%3};"
                            : "+f"(acc[mi][ni][0]), "+f"(acc[mi][ni][1]),
                              "+f"(acc[mi][ni][2]), "+f"(acc[mi][ni][3])
                            : "r"(af[mi][0]), "r"(af[mi][1]),
                              "r"(af[mi][2]), "r"(af[mi][3]),
                              "r"(bf[ni][0]), "r"(bf[ni][1]));
                    }
            }
            __syncthreads();
        }
    }

    if (EPI == 5) {
        // LSTM cell epilogue, float bias b1 (combined bih+bhh).
#pragma unroll
        for (int mi = 0; mi < 2; ++mi)
#pragma unroll
            for (int ni = 0; ni < 4; ++ni)
#pragma unroll
                for (int fr = 0; fr < 2; ++fr) {
                    int row = m0 + wm + mi * 16 + q + fr * 8;
                    int cb  = n0 + wn + ni * 8 + r * 2;
                    float v0 = acc[mi][ni][fr * 2 + 0] + b1[cb];
                    float v1 = acc[mi][ni][fr * 2 + 1] + b1[cb + 1];
                    bool ev = ((r & 1) == 0);
                    float a  = ev ? sigm(v0) : tanhf(v0);
                    float bb = sigm(v1);
                    float a2 = __shfl_xor_sync(0xffffffffu, a, 1);
                    float b2v = __shfl_xor_sync(0xffffffffu, bb, 1);
                    if (ev) {
                        size_t off = (size_t)row * HSZ + (cb >> 2);
                        float c2 = bb * Cs[off] + a * a2;
                        Cs[off] = c2;
                        Hs[off] = __float2half_rn(b2v * tanhf(c2));
                    }
                }
        return;
    }

    if (EPI == 6) {
        // K: [b, h, d/2, s, 2] fp16; half2 store per d-pair
#pragma unroll
        for (int mi = 0; mi < 2; ++mi)
#pragma unroll
            for (int ni = 0; ni < 4; ++ni)
#pragma unroll
                for (int fr = 0; fr < 2; ++fr) {
                    int m = m0 + wm + mi * 16 + q + fr * 8;
                    int n = n0 + wn + ni * 8 + r * 2;
                    float v0 = acc[mi][ni][fr * 2 + 0] + b1[n];
                    float v1 = acc[mi][ni][fr * 2 + 1] + b1[n + 1];
                    int b = m / SS, s = m - b * SS;
                    *reinterpret_cast<__half2*>(
                        C + (size_t)b * HSZ * SS + (size_t)n * SS + 2 * s) =
                        __floats2half2_rn(v0, v1);
                }
        return;
    }
    if (EPI == 7) {
        // V: [b, h, s, d] fp16
#pragma unroll
        for (int mi = 0; mi < 2; ++mi)
#pragma unroll
            for (int ni = 0; ni < 4; ++ni)
#pragma unroll
                for (int fr = 0; fr < 2; ++fr) {
                    int m = m0 + wm + mi * 16 + q + fr * 8;
                    int n = n0 + wn + ni * 8 + r * 2;
                    float v0 = acc[mi][ni][fr * 2 + 0] + b1[n];
                    float v1 = acc[mi][ni][fr * 2 + 1] + b1[n + 1];
                    int b = m / SS, s = m - b * SS;
                    int h = n >> 7, d = n & 127;
                    *reinterpret_cast<__half2*>(
                        C + (size_t)b * HSZ * SS + (size_t)h * SS * HD
                          + (size_t)s * HD + d) = __floats2half2_rn(v0, v1);
                }
        return;
    }

    // EPI 1/2/3: fp16 row-major stores (half2), optional bias + partial P
#pragma unroll
    for (int mi = 0; mi < 2; ++mi)
#pragma unroll
        for (int ni = 0; ni < 4; ++ni)
#pragma unroll
            for (int fr = 0; fr < 2; ++fr) {
                int m = m0 + wm + mi * 16 + q + fr * 8;
                int n = n0 + wn + ni * 8 + r * 2;
                float v0 = acc[mi][ni][fr * 2 + 0];
                float v1 = acc[mi][ni][fr * 2 + 1];
                if (b1) { v0 += b1[n]; v1 += b1[n + 1]; }
                if (P) {
                    float2 pf = __half22float2(
                        *(const __half2*)(P + (size_t)m * ldp + n));
                    v0 += pf.x; v1 += pf.y;
                }
                if (EPI == 1) {
                    v0 = (v0 >= 0.f) ? v0 : 0.2f * v0;
                    v1 = (v1 >= 0.f) ? v1 : 0.2f * v1;
                }
                if (EPI == 2) { v0 *= scale; v1 *= scale; }
                *reinterpret_cast<__half2*>(C + (size_t)m * N + n) =
                    __floats2half2_rn(v0, v1);
            }
}

// ---------------------------------------------------------------------------
// Attention: one block per (b,h). q fp16 (pre-scaled).
// ---------------------------------------------------------------------------
__global__ __launch_bounds__(128)
void attn_kernel(const __half* __restrict__ q, const __half* __restrict__ Kt,
                 const __half* __restrict__ V, __half* __restrict__ att)
{
    __shared__ float qs[HD];
    __shared__ float sc[128];
    __shared__ float red[128];

    const int bh = blockIdx.x;
    const int b = bh >> 2, h = bh & 3;
    const int tid = threadIdx.x;

    qs[tid] = __half2float(q[(size_t)b * HSZ + h * HD + tid]);
    __syncthreads();

    float a = 0.f;
    const __half2* Kp2 = reinterpret_cast<const __half2*>(
        Kt + (size_t)bh * HD * SS);
    if (tid < SS) {
        float a0 = 0.f, a1 = 0.f;
#pragma unroll 8
        for (int dp = 0; dp < 64; dp += 2) {
            float2 f0 = __half22float2(Kp2[(dp + 0) * SS + tid]);
            float2 f1 = __half22float2(Kp2[(dp + 1) * SS + tid]);
            a0 += qs[2 * dp + 0] * f0.x + qs[2 * dp + 1] * f0.y;
            a1 += qs[2 * dp + 2] * f1.x + qs[2 * dp + 3] * f1.y;
        }
        a = a0 + a1;
    }
    sc[tid] = a;
    red[tid] = (tid < SS) ? a : -1e30f;
    __syncthreads();
#pragma unroll
    for (int off = 64; off > 0; off >>= 1) {
        if (tid < off) red[tid] = fmaxf(red[tid], red[tid + off]);
        __syncthreads();
    }
    const float mx = red[0];
    __syncthreads();

    float e = (tid < SS) ? expf(sc[tid] - mx) : 0.f;
    sc[tid] = e;
    red[tid] = e;
    __syncthreads();
#pragma unroll
    for (int off = 64; off > 0; off >>= 1) {
        if (tid < off) red[tid] += red[tid + off];
        __syncthreads();
    }
    const float inv = 1.f / red[0];

    float o0 = 0.f, o1 = 0.f, o2 = 0.f, o3 = 0.f;
    const __half* Vp = V + (size_t)bh * SS * HD + tid;
#pragma unroll 2
    for (int s = 0; s < SS; s += 4) {
        o0 += sc[s + 0] * __half2float(Vp[(size_t)(s + 0) * HD]);
        o1 += sc[s + 1] * __half2float(Vp[(size_t)(s + 1) * HD]);
        o2 += sc[s + 2] * __half2float(Vp[(size_t)(s + 2) * HD]);
        o3 += sc[s + 3] * __half2float(Vp[(size_t)(s + 3) * HD]);
    }
    att[(size_t)b * HSZ + h * HD + tid] =
        __float2half_rn(((o0 + o1) + (o2 + o3)) * inv);
}

// ---------------------------------------------------------------------------
// Batched final layer over all (t, b): row m = t*BSN + b
// ---------------------------------------------------------------------------
__global__ __launch_bounds__(256)
void fc2c_all(const __half* __restrict__ y2, const float* __restrict__ w,
              const float* __restrict__ b, float* __restrict__ out)
{
    const int warp = threadIdx.x >> 5, lane = threadIdx.x & 31;
    const int m = blockIdx.x * 8 + warp;           // 0 .. TT*BSN-1
    const int t = m >> 10;                          // m / BSN
    const int bb = m & (BSN - 1);                   // m % BSN
    const __half* yr = y2 + (size_t)m * (HSZ / 4);
    float a0 = 0.f, a1 = 0.f;
#pragma unroll
    for (int d = lane; d < HSZ / 4; d += 32) {
        float v = __half2float(yr[d]);
        a0 += v * w[d];
        a1 += v * w[HSZ / 4 + d];
    }
#pragma unroll
    for (int off = 16; off; off >>= 1) {
        a0 += __shfl_down_sync(0xffffffff, a0, off);
        a1 += __shfl_down_sync(0xffffffff, a1, off);
    }
    if (lane == 0) {
        out[(size_t)bb * TT * OSZ + t * OSZ + 0] = tanhf(a0 + b[0]);
        out[(size_t)bb * TT * OSZ + t * OSZ + 1] = tanhf(a1 + b[1]);
    }
}

// ---------------------------------------------------------------------------
// Precompute kernels
// ---------------------------------------------------------------------------
__global__ void cvt2h(const float* __restrict__ in, __half* __restrict__ out,
                      int n4)
{
    int i = blockIdx.x * blockDim.x + threadIdx.x;
    if (i < n4) {
        float4 v = reinterpret_cast<const float4*>(in)[i];
        reinterpret_cast<__half2*>(out)[2 * i]     = __floats2half2_rn(v.x, v.y);
        reinterpret_cast<__half2*>(out)[2 * i + 1] = __floats2half2_rn(v.z, v.w);
    }
}

__global__ void transpose512h(const float* __restrict__ in, __half* __restrict__ out)
{
    __shared__ float t[32][33];
    int x = blockIdx.x * 32 + threadIdx.x;
    int y0 = blockIdx.y * 32 + threadIdx.y;
#pragma unroll
    for (int i = 0; i < 4; ++i)
        t[threadIdx.y + i * 8][threadIdx.x] = in[(size_t)(y0 + i * 8) * HSZ + x];
    __syncthreads();
    x = blockIdx.y * 32 + threadIdx.x;
    int y1 = blockIdx.x * 32 + threadIdx.y;
#pragma unroll
    for (int i = 0; i < 4; ++i)
        out[(size_t)(y1 + i * 8) * HSZ + x] =
            __float2half_rn(t[threadIdx.x][threadIdx.y + i * 8]);
}

__global__ void prep_fc1b(const float* __restrict__ fc1_w,
                          const float* __restrict__ out_b,
                          const float* __restrict__ fc1_b,
                          float* __restrict__ bc)
{
    const int warp = threadIdx.x >> 5, lane = threadIdx.x & 31;
    const int j = blockIdx.x * 8 + warp;
    float s = 0.f;
#pragma unroll
    for (int m = lane; m < HSZ; m += 32)
        s += fc1_w[(size_t)j * (HSZ + LSZ) + m] * out_b[m];
#pragma unroll
    for (int off = 16; off; off >>= 1)
        s += __shfl_down_sync(0xffffffff, s, off);
    if (lane == 0) bc[j] = s + fc1_b[j];
}

__global__ void prep_lstm(const float* __restrict__ wih, const float* __restrict__ whh,
                          const float* __restrict__ bih, const float* __restrict__ bhh,
                          __half* __restrict__ wih_p, __half* __restrict__ whh_p,
                          float* __restrict__ b_p)
{
    int idx = blockIdx.x * blockDim.x + threadIdx.x;
    int c = idx >> 9, k = idx & 511;
    int orig = (c & 3) * HSZ + (c >> 2);
    wih_p[idx] = __float2half_rn(wih[(size_t)orig * HSZ + k]);
    whh_p[idx] = __float2half_rn(whh[(size_t)orig * HSZ + k]);
    if (k == 0) b_p[c] = bih[orig] + bhh[orig];
}

__global__ void zero_states()
{
    int idx = blockIdx.x * blockDim.x + threadIdx.x;
    if (idx < BSN * HSZ) {
        g_h1[0][idx] = __half(0.f); g_h1[1][idx] = __half(0.f);
        g_h2[idx] = __half(0.f);    // h2 history slot 0
        g_c1[idx] = 0.f;            g_c2[idx] = 0.f;
    }
}

// ---------------------------------------------------------------------------
extern "C" void kernel_launch(void* const* d_in, const int* in_sizes, int n_in,
                              void* d_out, int out_size)
{
    (void)in_sizes; (void)n_in; (void)out_size;
    const float* encoded = (const float*)d_in[0];
    const float* z       = (const float*)d_in[1];
    const float* q_w     = (const float*)d_in[2];
    const float* k_w     = (const float*)d_in[3];
    const float* v_w     = (const float*)d_in[4];
    const float* q_b     = (const float*)d_in[5];
    const float* k_b     = (const float*)d_in[6];
    const float* v_b     = (const float*)d_in[7];
    const float* out_w   = (const float*)d_in[8];
    const float* out_b   = (const float*)d_in[9];
    const float* fc1_w   = (const float*)d_in[10];
    const float* fc1_b   = (const float*)d_in[11];
    const float* l1_wih  = (const float*)d_in[12];
    const float* l1_whh  = (const float*)d_in[13];
    const float* l1_bih  = (const float*)d_in[14];
    const float* l1_bhh  = (const float*)d_in[15];
    const float* l2_wih  = (const float*)d_in[16];
    const float* l2_whh  = (const float*)d_in[17];
    const float* l2_bih  = (const float*)d_in[18];
    const float* l2_bhh  = (const float*)d_in[19];
    const float* fc2a_w  = (const float*)d_in[20];
    const float* fc2a_b  = (const float*)d_in[21];
    const float* fc2b_w  = (const float*)d_in[22];
    const float* fc2b_b  = (const float*)d_in[23];
    const float* fc2c_w  = (const float*)d_in[24];
    const float* fc2c_b  = (const float*)d_in[25];
    float* out = (float*)d_out;

    __half *pK, *pV, *pq, *patt, *pf1, *ph1, *ph2, *py1, *py2, *pzf1;
    __half *pench, *pzh, *pqwh, *pkwh, *pvwh, *powTh, *pfc1wh, *pwch;
    __half *pl1wih, *pl1whh, *pl2wih, *pl2whh, *pfc2awh, *pfc2bwh;
    float *pc1, *pc2, *pbc, *pl1b, *pl2b;
    cudaGetSymbolAddress((void**)&pK,  g_K);
    cudaGetSymbolAddress((void**)&pV,  g_V);
    cudaGetSymbolAddress((void**)&pq,  g_q);
    cudaGetSymbolAddress((void**)&patt, g_att);
    cudaGetSymbolAddress((void**)&pf1, g_f1);
    cudaGetSymbolAddress((void**)&ph1, g_h1);
    cudaGetSymbolAddress((void**)&pc1, g_c1);
    cudaGetSymbolAddress((void**)&ph2, g_h2);
    cudaGetSymbolAddress((void**)&pc2, g_c2);
    cudaGetSymbolAddress((void**)&py1, g_y1);
    cudaGetSymbolAddress((void**)&py2, g_y2);
    cudaGetSymbolAddress((void**)&pzf1, g_zf1);
    cudaGetSymbolAddress((void**)&pench, g_ench);
    cudaGetSymbolAddress((void**)&pzh,   g_zh);
    cudaGetSymbolAddress((void**)&pqwh,  g_qwh);
    cudaGetSymbolAddress((void**)&pkwh,  g_kwh);
    cudaGetSymbolAddress((void**)&pvwh,  g_vwh);
    cudaGetSymbolAddress((void**)&powTh, g_owTh);
    cudaGetSymbolAddress((void**)&pfc1wh, g_fc1wh);
    cudaGetSymbolAddress((void**)&pwch,  g_wch);
    cudaGetSymbolAddress((void**)&pbc,   g_bc);
    cudaGetSymbolAddress((void**)&pl1wih, g_l1wih);
    cudaGetSymbolAddress((void**)&pl1whh, g_l1whh);
    cudaGetSymbolAddress((void**)&pl1b,   g_l1b);
    cudaGetSymbolAddress((void**)&pl2wih, g_l2wih);
    cudaGetSymbolAddress((void**)&pl2whh, g_l2whh);
    cudaGetSymbolAddress((void**)&pl2b,   g_l2b);
    cudaGetSymbolAddress((void**)&pfc2awh, g_fc2awh);
    cudaGetSymbolAddress((void**)&pfc2bwh, g_fc2bwh);

    const size_t SMH64   = (size_t)(4 * 64) * STRH * sizeof(__half);   // 20480
    const size_t SMH1212 = (size_t)(4 * 128) * STRH * sizeof(__half);  // 40960

    const float qscale = 0.08838834764831845f;  // 1/sqrt(128)

    // ---- precomputes ----
    zero_states<<<(BSN * HSZ + 255) / 256, 256>>>();
    cvt2h<<<((BSN * SS * ESZ / 4) + 255) / 256, 256>>>(encoded, pench, BSN * SS * ESZ / 4);
    cvt2h<<<((BSN * TT * LSZ / 4) + 255) / 256, 256>>>(z, pzh, BSN * TT * LSZ / 4);
    cvt2h<<<((HSZ * HSZ / 4) + 255) / 256, 256>>>(q_w, pqwh, HSZ * HSZ / 4);
    cvt2h<<<((HSZ * ESZ / 4) + 255) / 256, 256>>>(k_w, pkwh, HSZ * ESZ / 4);
    cvt2h<<<((HSZ * ESZ / 4) + 255) / 256, 256>>>(v_w, pvwh, HSZ * ESZ / 4);
    cvt2h<<<((HSZ * (HSZ + LSZ) / 4) + 255) / 256, 256>>>(fc1_w, pfc1wh, HSZ * (HSZ + LSZ) / 4);
    cvt2h<<<((HSZ / 2 * HSZ / 4) + 255) / 256, 256>>>(fc2a_w, pfc2awh, HSZ / 2 * HSZ / 4);
    cvt2h<<<((HSZ / 4 * HSZ / 2 / 4) + 255) / 256, 256>>>(fc2b_w, pfc2bwh, HSZ / 4 * HSZ / 2 / 4);
    transpose512h<<<dim3(16, 16), dim3(32, 8)>>>(out_w, powTh);
    prep_fc1b<<<64, 256>>>(fc1_w, out_b, fc1_b, pbc);
    prep_lstm<<<4096, 256>>>(l1_wih, l1_whh, l1_bih, l1_bhh, pl1wih, pl1whh, pl1b);
    prep_lstm<<<4096, 256>>>(l2_wih, l2_whh, l2_bih, l2_bhh, pl2wih, pl2whh, pl2b);
    // W_comb = fc1_A @ out_w
    hgemm<3, 64, 64><<<dim3(8, 8), 128, SMH64>>>(
        pfc1wh, HSZ + LSZ, HSZ, powTh, HSZ, nullptr, 0, 0, nullptr, 0,
        nullptr, nullptr, 0, pwch, HSZ, 0.f, nullptr, nullptr);
    // zf1[b*TT+t, n] = z[b,t,:] @ fc1_B^T + bc
    hgemm<3, 128, 128><<<dim3(HSZ / 128, (BSN * TT) / 128), 512, SMH1212>>>(
        pzh, LSZ, LSZ, pfc1wh + HSZ, HSZ + LSZ, nullptr, 0, 0, nullptr, 0,
        pbc, nullptr, 0, pzf1, HSZ, 0.f, nullptr, nullptr);

    // ---- K/V projections ----
    {
        dim3 grid(HSZ / 128, (BSN * SS) / 128);
        hgemm<6, 128, 128><<<grid, 512, SMH1212>>>(
            pench, ESZ, ESZ, pkwh, ESZ, nullptr, 0, 0, nullptr, 0,
            k_b, nullptr, 0, pK, HSZ, 0.f, nullptr, nullptr);
        hgemm<7, 128, 128><<<grid, 512, SMH1212>>>(
            pench, ESZ, ESZ, pvwh, ESZ, nullptr, 0, 0, nullptr, 0,
            v_b, nullptr, 0, pV, HSZ, 0.f, nullptr, nullptr);
    }

    dim3 gH(HSZ / 64, BSN / 64);             // 8 x 16
    dim3 gG(4 * HSZ / 128, BSN / 128);       // 16 x 8

    const size_t HB = (size_t)BSN * HSZ;

    // ---- recurrent loop: 5 kernel nodes per step, single stream, no events
    for (int t = 0; t < TT; ++t) {
        __half* h1r = ph1 + (t & 1) * HB;
        __half* h1w = ph1 + ((t + 1) & 1) * HB;
        __half* h2r = ph2 + (size_t)t * HB;        // history slot t
        __half* h2w = ph2 + (size_t)(t + 1) * HB;  // history slot t+1

        hgemm<2, 64, 64><<<gH, 128, SMH64>>>(
            h2r, HSZ, HSZ, pqwh, HSZ, nullptr, 0, 0, nullptr, 0,
            q_b, nullptr, 0, pq, HSZ, qscale, nullptr, nullptr);
        attn_kernel<<<BSN * NH, 128>>>(pq, pK, pV, patt);
        // fc1 single-pass: lrelu(att @ W_comb + zf1[t])
        hgemm<1, 64, 64><<<gH, 128, SMH64>>>(
            patt, HSZ, HSZ, pwch, HSZ, nullptr, 0, 0, nullptr, 0,
            nullptr, pzf1 + (size_t)t * HSZ, TT * HSZ,
            pf1, HSZ, 0.f, nullptr, nullptr);
        // LSTM1: gates = f1 @ wih + h1 @ whh + b  (dual-input, fp32 accum)
        hgemm<5, 128, 128><<<gG, 512, SMH1212>>>(
            pf1, HSZ, HSZ, pl1wih, HSZ, h1r, HSZ, HSZ, pl1whh, HSZ,
            pl1b, nullptr, 0, nullptr, 4 * HSZ, 0.f, h1w, pc1);
        // LSTM2: writes h2 history slot t+1
        hgemm<5, 128, 128><<<gG, 512, SMH1212>>>(
            h1w, HSZ, HSZ, pl2wih, HSZ, h2r, HSZ, HSZ, pl2whh, HSZ,
            pl2b, nullptr, 0, nullptr, 4 * HSZ, 0.f, h2w, pc2);
    }

    // ---- batched fc2 tail over all timesteps (rows m = t*BSN + b) ----
    // fc2a: [TT*BSN, 512] -> [TT*BSN, 256]
    hgemm<1, 64, 64><<<dim3((HSZ / 2) / 64, (TT * BSN) / 64), 128, SMH64>>>(
        ph2 + HB, HSZ, HSZ, pfc2awh, HSZ, nullptr, 0, 0, nullptr, 0,
        fc2a_b, nullptr, 0, py1, HSZ / 2, 0.f, nullptr, nullptr);
    // fc2b: [TT*BSN, 256] -> [TT*BSN, 128]
    hgemm<1, 64, 64><<<dim3((HSZ / 4) / 64, (TT * BSN) / 64), 128, SMH64>>>(
        py1, HSZ / 2, HSZ / 2, pfc2bwh, HSZ / 2, nullptr, 0, 0, nullptr, 0,
        fc2b_b, nullptr, 0, py2, HSZ / 4, 0.f, nullptr, nullptr);
    // fc2c: [TT*BSN, 128] -> out[b, t, 2]
    fc2c_all<<<(TT * BSN) / 8, 256>>>(py2, fc2c_w, fc2c_b, out);
}